// round 1
// baseline (speedup 1.0000x reference)
#include <cuda_runtime.h>

// Problem shape (fixed by the dataset):
//   pred_boxes: [16, 900, 4] fp32 (cxcywh)  -> 14400 preds
//   gt_boxes:   [1600, 4]    fp32 (cxcywh)
//   out:        [16, 900, 1600] fp32 cost = 5*L1 - 2*GIoU
#define MGT    1600
#define COLS4  (MGT / 4)            // 400 float4 columns per pred row
#define NPRED  (16 * 900)           // 14400
#define TOTAL4 (NPRED * COLS4)      // 5,760,000 float4 outputs
#define TPB    128

// GT-derived SoA table: rows = {cx, cy, w, h, x0, y0, x1, y1, area}
__device__ __align__(16) float g_gt[9][MGT];

__global__ void gt_pre_kernel(const float* __restrict__ gt) {
    int i = blockIdx.x * blockDim.x + threadIdx.x;
    if (i < MGT) {
        float4 b = reinterpret_cast<const float4*>(gt)[i];
        float x0 = b.x - 0.5f * b.z;
        float y0 = b.y - 0.5f * b.w;
        float x1 = b.x + 0.5f * b.z;
        float y1 = b.y + 0.5f * b.w;
        g_gt[0][i] = b.x;
        g_gt[1][i] = b.y;
        g_gt[2][i] = b.z;
        g_gt[3][i] = b.w;
        g_gt[4][i] = x0;
        g_gt[5][i] = y0;
        g_gt[6][i] = x1;
        g_gt[7][i] = y1;
        g_gt[8][i] = (x1 - x0) * (y1 - y0);
    }
}

__device__ __forceinline__ float cost_one(
    float pcx, float pcy, float pw, float ph,
    float px0, float py0, float px1, float py1, float pa,
    float gcx, float gcy, float gw, float gh,
    float gx0, float gy0, float gx1, float gy1, float ga)
{
    // L1 cdist over cxcywh (|src| on FADD operands is free in SASS)
    float l1 = fabsf(pcx - gcx) + fabsf(pcy - gcy) + fabsf(pw - gw) + fabsf(ph - gh);

    // Intersection
    float ix0 = fmaxf(px0, gx0);
    float iy0 = fmaxf(py0, gy0);
    float ix1 = fminf(px1, gx1);
    float iy1 = fminf(py1, gy1);
    float iw  = fmaxf(ix1 - ix0, 0.0f);
    float ih  = fmaxf(iy1 - iy0, 0.0f);
    float inter = iw * ih;

    float uni = pa + ga - inter;

    // Enclosing box (always non-degenerate: max-min >= 0, no clip needed)
    float ex0 = fminf(px0, gx0);
    float ey0 = fminf(py0, gy0);
    float ex1 = fmaxf(px1, gx1);
    float ey1 = fmaxf(py1, gy1);
    float ea  = (ex1 - ex0) * (ey1 - ey0);

    // giou = inter/uni - (ea - uni)/ea ; approx divides (MUFU.RCP) — well
    // inside the 1e-3 rel-err budget.
    float giou = __fdividef(inter, uni) - __fdividef(ea - uni, ea);

    return fmaf(5.0f, l1, -2.0f * giou);
}

__global__ void __launch_bounds__(TPB)
cost_kernel(const float* __restrict__ pred, float* __restrict__ out)
{
    int id = blockIdx.x * blockDim.x + threadIdx.x;
    if (id >= TOTAL4) return;

    int p = id / COLS4;          // pred row (compile-time const divisor -> mul/shift)
    int c = id - p * COLS4;      // float4 column within row

    // Pred box: broadcast load within the warp (1-2 distinct preds/warp)
    float4 pb = reinterpret_cast<const float4*>(pred)[p];
    float px0 = pb.x - 0.5f * pb.z;
    float py0 = pb.y - 0.5f * pb.w;
    float px1 = pb.x + 0.5f * pb.z;
    float py1 = pb.y + 0.5f * pb.w;
    float pa  = (px1 - px0) * (py1 - py0);

    // 9 coalesced LDG.128 from the hot GT table
    float4 gcx = reinterpret_cast<const float4*>(g_gt[0])[c];
    float4 gcy = reinterpret_cast<const float4*>(g_gt[1])[c];
    float4 gw  = reinterpret_cast<const float4*>(g_gt[2])[c];
    float4 gh  = reinterpret_cast<const float4*>(g_gt[3])[c];
    float4 gx0 = reinterpret_cast<const float4*>(g_gt[4])[c];
    float4 gy0 = reinterpret_cast<const float4*>(g_gt[5])[c];
    float4 gx1 = reinterpret_cast<const float4*>(g_gt[6])[c];
    float4 gy1 = reinterpret_cast<const float4*>(g_gt[7])[c];
    float4 ga  = reinterpret_cast<const float4*>(g_gt[8])[c];

    float4 res;
    res.x = cost_one(pb.x, pb.y, pb.z, pb.w, px0, py0, px1, py1, pa,
                     gcx.x, gcy.x, gw.x, gh.x, gx0.x, gy0.x, gx1.x, gy1.x, ga.x);
    res.y = cost_one(pb.x, pb.y, pb.z, pb.w, px0, py0, px1, py1, pa,
                     gcx.y, gcy.y, gw.y, gh.y, gx0.y, gy0.y, gx1.y, gy1.y, ga.y);
    res.z = cost_one(pb.x, pb.y, pb.z, pb.w, px0, py0, px1, py1, pa,
                     gcx.z, gcy.z, gw.z, gh.z, gx0.z, gy0.z, gx1.z, gy1.z, ga.z);
    res.w = cost_one(pb.x, pb.y, pb.z, pb.w, px0, py0, px1, py1, pa,
                     gcx.w, gcy.w, gw.w, gh.w, gx0.w, gy0.w, gx1.w, gy1.w, ga.w);

    reinterpret_cast<float4*>(out)[id] = res;
}

extern "C" void kernel_launch(void* const* d_in, const int* in_sizes, int n_in,
                              void* d_out, int out_size)
{
    (void)in_sizes; (void)n_in; (void)out_size;
    const float* pred = (const float*)d_in[0];
    const float* gt   = (const float*)d_in[1];
    float* out        = (float*)d_out;

    gt_pre_kernel<<<(MGT + TPB - 1) / TPB, TPB>>>(gt);
    cost_kernel<<<TOTAL4 / TPB, TPB>>>(pred, out);
}